// round 1
// baseline (speedup 1.0000x reference)
#include <cuda_runtime.h>

#define N 8192
#define N4 2048           // N / 4 (float4)
#define MARGIN 0.2f
#define INV_LAMB 83.333336f   // 1 / 0.012
#define ROWCHUNKS 128
#define ROWS_PER_CHUNK 64     // 8192 / 128

// ---- scratch (static __device__ globals; no allocations) ----
__device__ float g_r[N];                    // row scales a_i
__device__ float g_c[N];                    // col scales b_j
__device__ float g_d[N];                    // diagonal of P
__device__ float g_partial[ROWCHUNKS * N];  // col-pass partials (4 MB)
__device__ float g_row_loss[N];             // per-row loss partials

__device__ __forceinline__ float warp_sum(float v) {
    v += __shfl_xor_sync(0xffffffffu, v, 16);
    v += __shfl_xor_sync(0xffffffffu, v, 8);
    v += __shfl_xor_sync(0xffffffffu, v, 4);
    v += __shfl_xor_sync(0xffffffffu, v, 2);
    v += __shfl_xor_sync(0xffffffffu, v, 1);
    return v;
}

__device__ __forceinline__ float kval(float s) {
    return __expf((s - 1.0f) * INV_LAMB);
}

__global__ void init_c_kernel() {
    int j = blockIdx.x * blockDim.x + threadIdx.x;
    if (j < N) g_c[j] = 1.0f;
}

// r_i = 1 / sum_j K_ij * c_j     (one warp per row; 1024 blocks x 256 thr)
__global__ void row_pass_kernel(const float* __restrict__ sims) {
    int warp = threadIdx.x >> 5;
    int lane = threadIdx.x & 31;
    int row  = blockIdx.x * 8 + warp;
    const float4* __restrict__ s4 = (const float4*)(sims + (size_t)row * N);
    const float4* __restrict__ c4 = (const float4*)g_c;

    float ax = 0.f, ay = 0.f, az = 0.f, aw = 0.f;
    #pragma unroll 4
    for (int jv = lane; jv < N4; jv += 32) {
        float4 s = s4[jv];
        float4 c = c4[jv];
        ax += kval(s.x) * c.x;
        ay += kval(s.y) * c.y;
        az += kval(s.z) * c.z;
        aw += kval(s.w) * c.w;
    }
    float acc = warp_sum((ax + ay) + (az + aw));
    if (lane == 0) g_r[row] = 1.0f / acc;
}

// partial[rc][j] = sum over the chunk's rows of K_ij * r_i
// grid (8, 128): x = 1024-col chunk, y = 64-row chunk; block 256
__global__ void col_pass_kernel(const float* __restrict__ sims) {
    int jv = blockIdx.x * 256 + threadIdx.x;   // float4 column index (0..2047)
    int i0 = blockIdx.y * ROWS_PER_CHUNK;
    const float4* __restrict__ s4 = (const float4*)sims;

    float4 acc = make_float4(0.f, 0.f, 0.f, 0.f);
    #pragma unroll 4
    for (int k = 0; k < ROWS_PER_CHUNK; k++) {
        int i = i0 + k;
        float ri = g_r[i];
        float4 s = s4[(size_t)i * N4 + jv];
        acc.x += kval(s.x) * ri;
        acc.y += kval(s.y) * ri;
        acc.z += kval(s.z) * ri;
        acc.w += kval(s.w) * ri;
    }
    ((float4*)(g_partial + (size_t)blockIdx.y * N))[jv] = acc;
}

// c_j = 1 / sum_rc partial[rc][j]
__global__ void col_reduce_kernel() {
    int j = blockIdx.x * blockDim.x + threadIdx.x;
    float v = 0.f;
    #pragma unroll
    for (int rc = 0; rc < ROWCHUNKS; rc++) v += g_partial[rc * N + j];
    g_c[j] = 1.0f / v;
}

__global__ void diag_kernel(const float* __restrict__ sims) {
    int j = blockIdx.x * blockDim.x + threadIdx.x;
    if (j < N) g_d[j] = kval(sims[(size_t)j * N + j]) * g_r[j] * g_c[j];
}

// per-row hinge partials (one warp per row, like row_pass)
__global__ void loss_pass_kernel(const float* __restrict__ sims) {
    int warp = threadIdx.x >> 5;
    int lane = threadIdx.x & 31;
    int row  = blockIdx.x * 8 + warp;
    float ri = g_r[row];
    float di = g_d[row];
    const float4* __restrict__ s4 = (const float4*)(sims + (size_t)row * N);
    const float4* __restrict__ c4 = (const float4*)g_c;
    const float4* __restrict__ d4 = (const float4*)g_d;

    float a0 = 0.f, a1 = 0.f, a2 = 0.f, a3 = 0.f;
    #pragma unroll 2
    for (int jv = lane; jv < N4; jv += 32) {
        float4 s = s4[jv];
        float4 c = c4[jv];
        float4 dd = d4[jv];
        int jb = jv << 2;
        float P;
        P = kval(s.x) * ri * c.x;
        if (jb + 0 != row) a0 += fmaxf(P - dd.x + MARGIN, 0.f) + fmaxf(P - di + MARGIN, 0.f);
        P = kval(s.y) * ri * c.y;
        if (jb + 1 != row) a1 += fmaxf(P - dd.y + MARGIN, 0.f) + fmaxf(P - di + MARGIN, 0.f);
        P = kval(s.z) * ri * c.z;
        if (jb + 2 != row) a2 += fmaxf(P - dd.z + MARGIN, 0.f) + fmaxf(P - di + MARGIN, 0.f);
        P = kval(s.w) * ri * c.w;
        if (jb + 3 != row) a3 += fmaxf(P - dd.w + MARGIN, 0.f) + fmaxf(P - di + MARGIN, 0.f);
    }
    float acc = warp_sum((a0 + a1) + (a2 + a3));
    if (lane == 0) g_row_loss[row] = acc;
}

__global__ void final_reduce_kernel(float* __restrict__ out) {
    __shared__ double sh[256];
    double acc = 0.0;
    for (int i = threadIdx.x; i < N; i += 256) acc += (double)g_row_loss[i];
    sh[threadIdx.x] = acc;
    __syncthreads();
    #pragma unroll
    for (int s = 128; s > 0; s >>= 1) {
        if (threadIdx.x < s) sh[threadIdx.x] += sh[threadIdx.x + s];
        __syncthreads();
    }
    if (threadIdx.x == 0) out[0] = (float)sh[0];
}

extern "C" void kernel_launch(void* const* d_in, const int* in_sizes, int n_in,
                              void* d_out, int out_size) {
    const float* sims = (const float*)d_in[0];
    float* out = (float*)d_out;

    init_c_kernel<<<32, 256>>>();
    for (int it = 0; it < 5; it++) {
        row_pass_kernel<<<1024, 256>>>(sims);                  // a_i update
        col_pass_kernel<<<dim3(8, ROWCHUNKS), 256>>>(sims);    // col partials
        col_reduce_kernel<<<32, 256>>>();                      // b_j update
    }
    diag_kernel<<<32, 256>>>(sims);
    loss_pass_kernel<<<1024, 256>>>(sims);
    final_reduce_kernel<<<1, 256>>>(out);
}

// round 2
// speedup vs baseline: 1.0032x; 1.0032x over previous
#include <cuda_runtime.h>

#define N 8192
#define N4 2048           // N / 4 (float4)
#define MARGIN 0.2f
#define INV_LAMB 83.333336f   // 1 / 0.012
#define ROWCHUNKS 128
#define ROWS_PER_CHUNK 64     // 8192 / 128

// ---- scratch (static __device__ globals; no allocations) ----
__device__ float g_r[N];                    // row scales a_i
__device__ float g_c[N];                    // col scales b_j
__device__ float g_d[N];                    // diagonal of P
__device__ float g_partial[ROWCHUNKS * N];  // col-pass partials (4 MB)
__device__ float g_row_loss[N];             // per-row loss partials

__device__ __forceinline__ float warp_sum(float v) {
    v += __shfl_xor_sync(0xffffffffu, v, 16);
    v += __shfl_xor_sync(0xffffffffu, v, 8);
    v += __shfl_xor_sync(0xffffffffu, v, 4);
    v += __shfl_xor_sync(0xffffffffu, v, 2);
    v += __shfl_xor_sync(0xffffffffu, v, 1);
    return v;
}

__device__ __forceinline__ float kval(float s) {
    return __expf((s - 1.0f) * INV_LAMB);
}

__global__ void init_c_kernel() {
    int j = blockIdx.x * blockDim.x + threadIdx.x;
    if (j < N) g_c[j] = 1.0f;
}

// r_i = 1 / sum_j K_ij * c_j     (one warp per row; 1024 blocks x 256 thr)
__global__ void row_pass_kernel(const float* __restrict__ sims) {
    int warp = threadIdx.x >> 5;
    int lane = threadIdx.x & 31;
    int row  = blockIdx.x * 8 + warp;
    const float4* __restrict__ s4 = (const float4*)(sims + (size_t)row * N);
    const float4* __restrict__ c4 = (const float4*)g_c;

    float ax = 0.f, ay = 0.f, az = 0.f, aw = 0.f;
    #pragma unroll 4
    for (int jv = lane; jv < N4; jv += 32) {
        float4 s = s4[jv];
        float4 c = c4[jv];
        ax += kval(s.x) * c.x;
        ay += kval(s.y) * c.y;
        az += kval(s.z) * c.z;
        aw += kval(s.w) * c.w;
    }
    float acc = warp_sum((ax + ay) + (az + aw));
    if (lane == 0) g_r[row] = 1.0f / acc;
}

// partial[rc][j] = sum over the chunk's rows of K_ij * r_i
// grid (8, 128): x = 1024-col chunk, y = 64-row chunk; block 256
__global__ void col_pass_kernel(const float* __restrict__ sims) {
    int jv = blockIdx.x * 256 + threadIdx.x;   // float4 column index (0..2047)
    int i0 = blockIdx.y * ROWS_PER_CHUNK;
    const float4* __restrict__ s4 = (const float4*)sims;

    float4 acc = make_float4(0.f, 0.f, 0.f, 0.f);
    #pragma unroll 4
    for (int k = 0; k < ROWS_PER_CHUNK; k++) {
        int i = i0 + k;
        float ri = g_r[i];
        float4 s = s4[(size_t)i * N4 + jv];
        acc.x += kval(s.x) * ri;
        acc.y += kval(s.y) * ri;
        acc.z += kval(s.z) * ri;
        acc.w += kval(s.w) * ri;
    }
    ((float4*)(g_partial + (size_t)blockIdx.y * N))[jv] = acc;
}

// c_j = 1 / sum_rc partial[rc][j]
__global__ void col_reduce_kernel() {
    int j = blockIdx.x * blockDim.x + threadIdx.x;
    float v = 0.f;
    #pragma unroll
    for (int rc = 0; rc < ROWCHUNKS; rc++) v += g_partial[rc * N + j];
    g_c[j] = 1.0f / v;
}

__global__ void diag_kernel(const float* __restrict__ sims) {
    int j = blockIdx.x * blockDim.x + threadIdx.x;
    if (j < N) g_d[j] = kval(sims[(size_t)j * N + j]) * g_r[j] * g_c[j];
}

// per-row hinge partials (one warp per row, like row_pass)
__global__ void loss_pass_kernel(const float* __restrict__ sims) {
    int warp = threadIdx.x >> 5;
    int lane = threadIdx.x & 31;
    int row  = blockIdx.x * 8 + warp;
    float ri = g_r[row];
    float di = g_d[row];
    const float4* __restrict__ s4 = (const float4*)(sims + (size_t)row * N);
    const float4* __restrict__ c4 = (const float4*)g_c;
    const float4* __restrict__ d4 = (const float4*)g_d;

    float a0 = 0.f, a1 = 0.f, a2 = 0.f, a3 = 0.f;
    #pragma unroll 2
    for (int jv = lane; jv < N4; jv += 32) {
        float4 s = s4[jv];
        float4 c = c4[jv];
        float4 dd = d4[jv];
        int jb = jv << 2;
        float P;
        P = kval(s.x) * ri * c.x;
        if (jb + 0 != row) a0 += fmaxf(P - dd.x + MARGIN, 0.f) + fmaxf(P - di + MARGIN, 0.f);
        P = kval(s.y) * ri * c.y;
        if (jb + 1 != row) a1 += fmaxf(P - dd.y + MARGIN, 0.f) + fmaxf(P - di + MARGIN, 0.f);
        P = kval(s.z) * ri * c.z;
        if (jb + 2 != row) a2 += fmaxf(P - dd.z + MARGIN, 0.f) + fmaxf(P - di + MARGIN, 0.f);
        P = kval(s.w) * ri * c.w;
        if (jb + 3 != row) a3 += fmaxf(P - dd.w + MARGIN, 0.f) + fmaxf(P - di + MARGIN, 0.f);
    }
    float acc = warp_sum((a0 + a1) + (a2 + a3));
    if (lane == 0) g_row_loss[row] = acc;
}

__global__ void final_reduce_kernel(float* __restrict__ out) {
    __shared__ double sh[256];
    double acc = 0.0;
    for (int i = threadIdx.x; i < N; i += 256) acc += (double)g_row_loss[i];
    sh[threadIdx.x] = acc;
    __syncthreads();
    #pragma unroll
    for (int s = 128; s > 0; s >>= 1) {
        if (threadIdx.x < s) sh[threadIdx.x] += sh[threadIdx.x + s];
        __syncthreads();
    }
    if (threadIdx.x == 0) out[0] = (float)sh[0];
}

extern "C" void kernel_launch(void* const* d_in, const int* in_sizes, int n_in,
                              void* d_out, int out_size) {
    const float* sims = (const float*)d_in[0];
    float* out = (float*)d_out;

    init_c_kernel<<<32, 256>>>();
    for (int it = 0; it < 5; it++) {
        row_pass_kernel<<<1024, 256>>>(sims);                  // a_i update
        col_pass_kernel<<<dim3(8, ROWCHUNKS), 256>>>(sims);    // col partials
        col_reduce_kernel<<<32, 256>>>();                      // b_j update
    }
    diag_kernel<<<32, 256>>>(sims);
    loss_pass_kernel<<<1024, 256>>>(sims);
    final_reduce_kernel<<<1, 256>>>(out);
}

// round 3
// speedup vs baseline: 1.3400x; 1.3357x over previous
#include <cuda_runtime.h>
#include <cuda_bf16.h>

#define N 8192
#define N4 2048           // N / 4  (float4 count per row)
#define N8 1024           // N / 8  (uint4-of-bf16 count per row)
#define MARGIN 0.2f
#define INV_LAMB 83.333336f   // 1 / 0.012
#define ROWCHUNKS 128
#define ROWS_PER_CHUNK 64     // 8192 / 128

// ---- scratch (static __device__ globals; no allocations) ----
__device__ uint4  g_K4[(size_t)N * N / 8];   // K in bf16, packed 8/uint4 (128 MB)
__device__ float  g_r[N];                    // row scales a_i
__device__ float  g_c[N];                    // col scales b_j
__device__ float  g_d[N];                    // diagonal of P
__device__ float  g_partial[ROWCHUNKS * N];  // col-pass partials (4 MB)
__device__ float  g_row_loss[N];             // per-row loss partials

__device__ __forceinline__ float warp_sum(float v) {
    v += __shfl_xor_sync(0xffffffffu, v, 16);
    v += __shfl_xor_sync(0xffffffffu, v, 8);
    v += __shfl_xor_sync(0xffffffffu, v, 4);
    v += __shfl_xor_sync(0xffffffffu, v, 2);
    v += __shfl_xor_sync(0xffffffffu, v, 1);
    return v;
}

__device__ __forceinline__ float kval(float s) {
    return __expf((s - 1.0f) * INV_LAMB);
}

__device__ __forceinline__ unsigned pack_bf2(float lo, float hi) {
    __nv_bfloat162 h = __floats2bfloat162_rn(lo, hi);
    return *reinterpret_cast<unsigned*>(&h);
}

__device__ __forceinline__ float2 unpack_bf2(unsigned u) {
    float2 f;
    f.x = __uint_as_float(u << 16);
    f.y = __uint_as_float(u & 0xffff0000u);
    return f;
}

// Pass 1: compute K = exp((s-1)/lamb), write bf16 cache, and do the first
// row update with c == 1:  r_i = 1 / sum_j K_ij.   One warp per row.
__global__ void pass1_kernel(const float* __restrict__ sims) {
    int warp = threadIdx.x >> 5;
    int lane = threadIdx.x & 31;
    int row  = blockIdx.x * 8 + warp;
    const float4* __restrict__ s4 = (const float4*)(sims + (size_t)row * N);
    uint4* __restrict__ k4 = g_K4 + (size_t)row * N8;

    float acc = 0.f;
    #pragma unroll 2
    for (int v = lane; v < N8; v += 32) {
        float4 a = s4[2 * v];
        float4 b = s4[2 * v + 1];
        float k0 = kval(a.x), k1 = kval(a.y), k2 = kval(a.z), k3 = kval(a.w);
        float k4v = kval(b.x), k5 = kval(b.y), k6 = kval(b.z), k7 = kval(b.w);
        acc += ((k0 + k1) + (k2 + k3)) + ((k4v + k5) + (k6 + k7));
        uint4 o;
        o.x = pack_bf2(k0, k1);
        o.y = pack_bf2(k2, k3);
        o.z = pack_bf2(k4v, k5);
        o.w = pack_bf2(k6, k7);
        k4[v] = o;
    }
    acc = warp_sum(acc);
    if (lane == 0) g_r[row] = 1.0f / acc;
}

// r_i = 1 / sum_j K_ij * c_j   (bf16 K; one warp per row)
__global__ void row_pass_bf16(void) {
    int warp = threadIdx.x >> 5;
    int lane = threadIdx.x & 31;
    int row  = blockIdx.x * 8 + warp;
    const uint4*  __restrict__ k4 = g_K4 + (size_t)row * N8;
    const float4* __restrict__ c4 = (const float4*)g_c;

    float a0 = 0.f, a1 = 0.f, a2 = 0.f, a3 = 0.f;
    #pragma unroll 2
    for (int v = lane; v < N8; v += 32) {
        uint4 k = k4[v];
        float4 c0 = c4[2 * v];
        float4 c1 = c4[2 * v + 1];
        float2 p;
        p = unpack_bf2(k.x); a0 += p.x * c0.x; a1 += p.y * c0.y;
        p = unpack_bf2(k.y); a2 += p.x * c0.z; a3 += p.y * c0.w;
        p = unpack_bf2(k.z); a0 += p.x * c1.x; a1 += p.y * c1.y;
        p = unpack_bf2(k.w); a2 += p.x * c1.z; a3 += p.y * c1.w;
    }
    float acc = warp_sum((a0 + a1) + (a2 + a3));
    if (lane == 0) g_r[row] = 1.0f / acc;
}

// partial[rc][j] = sum over chunk rows of K_ij * r_i   (bf16 K)
// grid (4, 128): x = 2048-col chunk (256 thr * 8 cols), y = 64-row chunk
__global__ void col_pass_bf16(void) {
    int v  = blockIdx.x * 256 + threadIdx.x;   // uint4 column index (0..1023)
    int i0 = blockIdx.y * ROWS_PER_CHUNK;

    float acc0 = 0.f, acc1 = 0.f, acc2 = 0.f, acc3 = 0.f;
    float acc4 = 0.f, acc5 = 0.f, acc6 = 0.f, acc7 = 0.f;
    #pragma unroll 4
    for (int k = 0; k < ROWS_PER_CHUNK; k++) {
        int i = i0 + k;
        float ri = g_r[i];
        uint4 kk = g_K4[(size_t)i * N8 + v];
        float2 p;
        p = unpack_bf2(kk.x); acc0 += p.x * ri; acc1 += p.y * ri;
        p = unpack_bf2(kk.y); acc2 += p.x * ri; acc3 += p.y * ri;
        p = unpack_bf2(kk.z); acc4 += p.x * ri; acc5 += p.y * ri;
        p = unpack_bf2(kk.w); acc6 += p.x * ri; acc7 += p.y * ri;
    }
    float4* out = (float4*)(g_partial + (size_t)blockIdx.y * N);
    out[2 * v]     = make_float4(acc0, acc1, acc2, acc3);
    out[2 * v + 1] = make_float4(acc4, acc5, acc6, acc7);
}

// c_j = 1 / sum_rc partial[rc][j]   (vectorized: thread = 4 columns)
__global__ void col_reduce_kernel(void) {
    int jv = blockIdx.x * 256 + threadIdx.x;   // float4 index 0..2047
    float4 acc = make_float4(0.f, 0.f, 0.f, 0.f);
    #pragma unroll
    for (int rc = 0; rc < ROWCHUNKS; rc++) {
        float4 p = ((const float4*)(g_partial + (size_t)rc * N))[jv];
        acc.x += p.x; acc.y += p.y; acc.z += p.z; acc.w += p.w;
    }
    float4 c;
    c.x = 1.0f / acc.x; c.y = 1.0f / acc.y;
    c.z = 1.0f / acc.z; c.w = 1.0f / acc.w;
    ((float4*)g_c)[jv] = c;
}

__global__ void diag_kernel(void) {
    int j = blockIdx.x * blockDim.x + threadIdx.x;
    const __nv_bfloat16* K = (const __nv_bfloat16*)g_K4;
    g_d[j] = __bfloat162float(K[(size_t)j * N + j]) * g_r[j] * g_c[j];
}

// per-row hinge partials (one warp per row; bf16 K)
__global__ void loss_pass_bf16(void) {
    int warp = threadIdx.x >> 5;
    int lane = threadIdx.x & 31;
    int row  = blockIdx.x * 8 + warp;
    float ri = g_r[row];
    float di = g_d[row];
    const uint4*  __restrict__ k4 = g_K4 + (size_t)row * N8;
    const float4* __restrict__ c4 = (const float4*)g_c;
    const float4* __restrict__ d4 = (const float4*)g_d;

    float a0 = 0.f, a1 = 0.f, a2 = 0.f, a3 = 0.f;
    #pragma unroll 2
    for (int v = lane; v < N8; v += 32) {
        uint4 k = k4[v];
        float4 c0 = c4[2 * v];
        float4 c1 = c4[2 * v + 1];
        float4 dd0 = d4[2 * v];
        float4 dd1 = d4[2 * v + 1];
        int jb = v << 3;
        float2 p; float P;

        p = unpack_bf2(k.x);
        P = p.x * ri * c0.x;
        if (jb + 0 != row) a0 += fmaxf(P - dd0.x + MARGIN, 0.f) + fmaxf(P - di + MARGIN, 0.f);
        P = p.y * ri * c0.y;
        if (jb + 1 != row) a1 += fmaxf(P - dd0.y + MARGIN, 0.f) + fmaxf(P - di + MARGIN, 0.f);

        p = unpack_bf2(k.y);
        P = p.x * ri * c0.z;
        if (jb + 2 != row) a2 += fmaxf(P - dd0.z + MARGIN, 0.f) + fmaxf(P - di + MARGIN, 0.f);
        P = p.y * ri * c0.w;
        if (jb + 3 != row) a3 += fmaxf(P - dd0.w + MARGIN, 0.f) + fmaxf(P - di + MARGIN, 0.f);

        p = unpack_bf2(k.z);
        P = p.x * ri * c1.x;
        if (jb + 4 != row) a0 += fmaxf(P - dd1.x + MARGIN, 0.f) + fmaxf(P - di + MARGIN, 0.f);
        P = p.y * ri * c1.y;
        if (jb + 5 != row) a1 += fmaxf(P - dd1.y + MARGIN, 0.f) + fmaxf(P - di + MARGIN, 0.f);

        p = unpack_bf2(k.w);
        P = p.x * ri * c1.z;
        if (jb + 6 != row) a2 += fmaxf(P - dd1.z + MARGIN, 0.f) + fmaxf(P - di + MARGIN, 0.f);
        P = p.y * ri * c1.w;
        if (jb + 7 != row) a3 += fmaxf(P - dd1.w + MARGIN, 0.f) + fmaxf(P - di + MARGIN, 0.f);
    }
    float acc = warp_sum((a0 + a1) + (a2 + a3));
    if (lane == 0) g_row_loss[row] = acc;
}

__global__ void final_reduce_kernel(float* __restrict__ out) {
    __shared__ double sh[256];
    double acc = 0.0;
    for (int i = threadIdx.x; i < N; i += 256) acc += (double)g_row_loss[i];
    sh[threadIdx.x] = acc;
    __syncthreads();
    #pragma unroll
    for (int s = 128; s > 0; s >>= 1) {
        if (threadIdx.x < s) sh[threadIdx.x] += sh[threadIdx.x + s];
        __syncthreads();
    }
    if (threadIdx.x == 0) out[0] = (float)sh[0];
}

extern "C" void kernel_launch(void* const* d_in, const int* in_sizes, int n_in,
                              void* d_out, int out_size) {
    const float* sims = (const float*)d_in[0];
    float* out = (float*)d_out;

    // iteration 0 row update fused with K materialization (c == 1)
    pass1_kernel<<<1024, 256>>>(sims);
    col_pass_bf16<<<dim3(4, ROWCHUNKS), 256>>>();
    col_reduce_kernel<<<8, 256>>>();

    for (int it = 1; it < 5; it++) {
        row_pass_bf16<<<1024, 256>>>();
        col_pass_bf16<<<dim3(4, ROWCHUNKS), 256>>>();
        col_reduce_kernel<<<8, 256>>>();
    }

    diag_kernel<<<32, 256>>>();
    loss_pass_bf16<<<1024, 256>>>();
    final_reduce_kernel<<<1, 256>>>(out);
}